// round 15
// baseline (speedup 1.0000x reference)
#include <cuda_runtime.h>
#include <cuda_fp16.h>
#include <cstdint>

#define BB 8
#define HH 512
#define EE 256
#define TT 2048
#define SS 2048
#define SCALE 0.8366600265340756f  // sqrt(0.7)

// ---- fp16 hi/lo scratch (device globals; no allocation in kernel_launch) ----
__device__ __half g_QH[BB * TT * EE],  g_QL[BB * TT * EE];
__device__ __half g_aH[(size_t)BB * TT * SS];
__device__ __half g_cH[BB * TT * EE];
__device__ __half g_VtH[BB * EE * SS];
__device__ __half g_dtH[BB * TT * HH], g_dtL[BB * TT * HH];
__device__ __half g_KH[BB * SS * EE],  g_KL[BB * SS * EE];
__device__ __half g_WqH[EE * HH], g_WqL[EE * HH];
__device__ __half g_WoH[HH * EE];

__device__ __forceinline__ uint32_t smem_u32(const void* p) {
    uint32_t a;
    asm("{ .reg .u64 t; cvta.to.shared.u64 t, %1; cvt.u32.u64 %0, t; }" : "=r"(a) : "l"(p));
    return a;
}
#define CPA16(dst, src) \
    asm volatile("cp.async.ca.shared.global [%0], [%1], 16;" :: "r"(dst), "l"(src))
#define CPA_COMMIT() asm volatile("cp.async.commit_group;" ::: "memory")
#define CPA_WAIT(n)  asm volatile("cp.async.wait_group %0;" :: "n"(n) : "memory")
#define LDM4(r0, r1, r2, r3, addr)                                            \
    asm volatile("ldmatrix.sync.aligned.m8n8.x4.shared.b16 {%0,%1,%2,%3}, [%4];" \
        : "=r"(r0), "=r"(r1), "=r"(r2), "=r"(r3) : "r"(addr))
#define MMA16(c, a, b)                                                        \
    asm volatile("mma.sync.aligned.m16n8k16.row.col.f32.f16.f16.f32 "         \
        "{%0,%1,%2,%3},{%4,%5,%6,%7},{%8,%9},{%0,%1,%2,%3};"                  \
        : "+f"((c)[0]), "+f"((c)[1]), "+f"((c)[2]), "+f"((c)[3])              \
        : "r"((a)[0]), "r"((a)[1]), "r"((a)[2]), "r"((a)[3]),                 \
          "r"((b)[0]), "r"((b)[1]))

// ==================== fp16 split GEMM ====================
// C[m,n] = sum_k A[m,k]*B[n,k]; A/B K-major fp16 hi(+lo).
// TERMS==3: Ah*Bh + Al*Bh + Ah*Bl (all f32 acc).  TERMS==1: Ah*Bh.
// 256 thr = 8 warps (2x4), warp tile 64x32, BK=32, cp.async double-buffered.
// SMEM stage (pitch 40 halves = 80B): Ah@0, Al@10240, Bh@20480, Bl@30720.
#define STAGE_B 40960
#define GEMMH_SMEM (2 * STAGE_B)

template <int TERMS>
__device__ __forceinline__ void load_tiles(
    uint32_t smb, int st,
    const __half* Ah, const __half* Al, int lda,
    const __half* Bh, const __half* Bl, int ldb,
    int k0, int tid)
{
    const int row = tid >> 1;
    const int hq  = (tid & 1) * 16;
    const uint32_t d0 = smb + (uint32_t)st * STAGE_B + (uint32_t)row * 80u
                        + (uint32_t)(tid & 1) * 32u;
    const size_t sa = (size_t)row * lda + k0 + hq;
    const size_t sb = (size_t)row * ldb + k0 + hq;
    CPA16(d0 +     0, Ah + sa); CPA16(d0 +    16, Ah + sa + 8);
    if (TERMS == 3) {
        CPA16(d0 + 10240, Al + sa); CPA16(d0 + 10256, Al + sa + 8);
        CPA16(d0 + 30720, Bl + sb); CPA16(d0 + 30736, Bl + sb + 8);
    }
    CPA16(d0 + 20480, Bh + sb); CPA16(d0 + 20496, Bh + sb + 8);
}

template <int TERMS>
__global__ void __launch_bounds__(256, 2) gemmh(
    const __half* __restrict__ AH, const __half* __restrict__ AL, int lda, size_t sA,
    const __half* __restrict__ BH, const __half* __restrict__ BL, int ldb, size_t sB,
    float* __restrict__ C, __half* __restrict__ CH, __half* __restrict__ CL,
    int ldc, size_t sC, int K, int mode,
    const float* __restrict__ bias,
    const float* __restrict__ aux, int ldaux, size_t saux)
{
    extern __shared__ __align__(16) char smraw[];
    const uint32_t smb = smem_u32(smraw);

    const int tid  = threadIdx.x;
    const int lane = tid & 31;
    const int wid  = tid >> 5;
    const int mB   = (wid >> 2) * 64;
    const int nB   = (wid & 3) * 32;
    const int g    = lane >> 2;
    const int tg   = lane & 3;
    const int l15  = lane & 15;
    const int lhi  = lane >> 4;

    const uint32_t aoff = (uint32_t)((mB + l15) * 80 + lhi * 16);
    const uint32_t boff = (uint32_t)((nB + l15) * 80 + lhi * 16);

    const int bz = blockIdx.z;
    const __half* Ah = AH + bz * sA + (size_t)(blockIdx.y * 128) * lda;
    const __half* Al = (TERMS == 3) ? AL + bz * sA + (size_t)(blockIdx.y * 128) * lda : nullptr;
    const __half* Bh = BH + bz * sB + (size_t)(blockIdx.x * 128) * ldb;
    const __half* Bl = (TERMS == 3) ? BL + bz * sB + (size_t)(blockIdx.x * 128) * ldb : nullptr;

    const int NC = K >> 5;
    float acc[4][4][4] = {};

    load_tiles<TERMS>(smb, 0, Ah, Al, lda, Bh, Bl, ldb, 0, tid);
    CPA_COMMIT();

    for (int c = 0; c < NC; c++) {
        if (c + 1 < NC) {
            load_tiles<TERMS>(smb, (c + 1) & 1, Ah, Al, lda, Bh, Bl, ldb, (c + 1) << 5, tid);
            CPA_COMMIT();
            CPA_WAIT(1);
        } else {
            CPA_WAIT(0);
        }
        __syncthreads();

        const uint32_t sb = smb + (uint32_t)(c & 1) * STAGE_B;
#pragma unroll
        for (int ks = 0; ks < 2; ks++) {
            const uint32_t ko = (uint32_t)ks * 32;
            uint32_t ah[4][4], al[4][4], bh[4][2], bl[4][2];
#pragma unroll
            for (int mi = 0; mi < 4; mi++) {
                LDM4(ah[mi][0], ah[mi][1], ah[mi][2], ah[mi][3],
                     sb + aoff + (uint32_t)mi * 1280 + ko);
                if (TERMS == 3)
                    LDM4(al[mi][0], al[mi][1], al[mi][2], al[mi][3],
                         sb + 10240 + aoff + (uint32_t)mi * 1280 + ko);
            }
#pragma unroll
            for (int nj = 0; nj < 2; nj++)
                LDM4(bh[2 * nj][0], bh[2 * nj + 1][0], bh[2 * nj][1], bh[2 * nj + 1][1],
                     sb + 20480 + boff + (uint32_t)nj * 1280 + ko);
            if (TERMS == 3) {
#pragma unroll
                for (int nj = 0; nj < 2; nj++)
                    LDM4(bl[2 * nj][0], bl[2 * nj + 1][0], bl[2 * nj][1], bl[2 * nj + 1][1],
                         sb + 30720 + boff + (uint32_t)nj * 1280 + ko);
            }

            // pass 1: hh
#pragma unroll
            for (int mi = 0; mi < 4; mi++)
#pragma unroll
                for (int ni = 0; ni < 4; ni++)
                    MMA16(acc[mi][ni], ah[mi], bh[ni]);
            if (TERMS == 3) {
                // pass 2: lh
#pragma unroll
                for (int mi = 0; mi < 4; mi++)
#pragma unroll
                    for (int ni = 0; ni < 4; ni++)
                        MMA16(acc[mi][ni], al[mi], bh[ni]);
                // pass 3: hl
#pragma unroll
                for (int mi = 0; mi < 4; mi++)
#pragma unroll
                    for (int ni = 0; ni < 4; ni++)
                        MMA16(acc[mi][ni], ah[mi], bl[ni]);
            }
        }
        __syncthreads();
    }

    // ---- epilogue ----
    if (mode == 0) {
        // plain fp32 store (energy)
        float* Cb = C + bz * sC;
#pragma unroll
        for (int mi = 0; mi < 4; mi++) {
            const int r = blockIdx.y * 128 + mB + mi * 16 + g;
#pragma unroll
            for (int ni = 0; ni < 4; ni++) {
                const int cc = blockIdx.x * 128 + nB + ni * 8 + 2 * tg;
                float2 v0 = {acc[mi][ni][0], acc[mi][ni][1]};
                float2 v1 = {acc[mi][ni][2], acc[mi][ni][3]};
                *(float2*)(Cb + (size_t)r * ldc + cc) = v0;
                *(float2*)(Cb + (size_t)(r + 8) * ldc + cc) = v1;
            }
        }
    } else if (mode == 2) {
        // transposed fp32 store + bias + residual + scale (output projection)
        float* Cb = C + bz * sC;
        const float* Db = aux + bz * saux;
#pragma unroll
        for (int mi = 0; mi < 4; mi++) {
            const int r = blockIdx.y * 128 + mB + mi * 16 + g;
#pragma unroll
            for (int ni = 0; ni < 4; ni++) {
                const int cc = blockIdx.x * 128 + nB + ni * 8 + 2 * tg;
                const float b0 = bias[cc], b1 = bias[cc + 1];
                Cb[(size_t)cc * ldc + r] =
                    SCALE * (acc[mi][ni][0] + b0 + Db[(size_t)cc * ldaux + r]);
                Cb[(size_t)(cc + 1) * ldc + r] =
                    SCALE * (acc[mi][ni][1] + b1 + Db[(size_t)(cc + 1) * ldaux + r]);
                Cb[(size_t)cc * ldc + r + 8] =
                    SCALE * (acc[mi][ni][2] + b0 + Db[(size_t)cc * ldaux + r + 8]);
                Cb[(size_t)(cc + 1) * ldc + r + 8] =
                    SCALE * (acc[mi][ni][3] + b1 + Db[(size_t)(cc + 1) * ldaux + r + 8]);
            }
        }
    } else if (mode == 1) {
        // fp16 hi/lo store + bias + emb + scale (Q projection)
        __half* CHb = CH + bz * sC;
        __half* CLb = CL + bz * sC;
#pragma unroll
        for (int mi = 0; mi < 4; mi++) {
            const int r = blockIdx.y * 128 + mB + mi * 16 + g;
#pragma unroll
            for (int ni = 0; ni < 4; ni++) {
                const int cc = blockIdx.x * 128 + nB + ni * 8 + 2 * tg;
                const float2 bi = *(const float2*)(bias + cc);
                const float2 e0 = *(const float2*)(aux + bz * saux + (size_t)r * ldaux + cc);
                const float2 e1 = *(const float2*)(aux + bz * saux + (size_t)(r + 8) * ldaux + cc);
                float q0 = SCALE * (acc[mi][ni][0] + bi.x + e0.x);
                float q1 = SCALE * (acc[mi][ni][1] + bi.y + e0.y);
                float q2 = SCALE * (acc[mi][ni][2] + bi.x + e1.x);
                float q3 = SCALE * (acc[mi][ni][3] + bi.y + e1.y);
                __half2 h0 = __floats2half2_rn(q0, q1);
                float2 f0 = __half22float2(h0);
                __half2 l0 = __floats2half2_rn(q0 - f0.x, q1 - f0.y);
                __half2 h1 = __floats2half2_rn(q2, q3);
                float2 f1 = __half22float2(h1);
                __half2 l1 = __floats2half2_rn(q2 - f1.x, q3 - f1.y);
                *(__half2*)(CHb + (size_t)r * ldc + cc) = h0;
                *(__half2*)(CLb + (size_t)r * ldc + cc) = l0;
                *(__half2*)(CHb + (size_t)(r + 8) * ldc + cc) = h1;
                *(__half2*)(CLb + (size_t)(r + 8) * ldc + cc) = l1;
            }
        }
    } else {
        // mode 3: fp16 hi-only store (context)
        __half* CHb = CH + bz * sC;
#pragma unroll
        for (int mi = 0; mi < 4; mi++) {
            const int r = blockIdx.y * 128 + mB + mi * 16 + g;
#pragma unroll
            for (int ni = 0; ni < 4; ni++) {
                const int cc = blockIdx.x * 128 + nB + ni * 8 + 2 * tg;
                *(__half2*)(CHb + (size_t)r * ldc + cc) =
                    __floats2half2_rn(acc[mi][ni][0], acc[mi][ni][1]);
                *(__half2*)(CHb + (size_t)(r + 8) * ldc + cc) =
                    __floats2half2_rn(acc[mi][ni][2], acc[mi][ni][3]);
            }
        }
    }
}

// ==================== prep: elementwise fp32 -> hi(+lo) fp16 ====================
__global__ void __launch_bounds__(256) split_plain(
    const float* __restrict__ s, __half* __restrict__ dH, __half* __restrict__ dL)
{
    const size_t i4 = ((size_t)blockIdx.x * 256 + threadIdx.x) * 4;
    float4 v = *(const float4*)(s + i4);
    __half2 h01 = __floats2half2_rn(v.x, v.y);
    __half2 h23 = __floats2half2_rn(v.z, v.w);
    ((__half2*)dH)[i4 >> 1] = h01; ((__half2*)dH)[(i4 >> 1) + 1] = h23;
    if (dL) {
        float2 f01 = __half22float2(h01);
        float2 f23 = __half22float2(h23);
        ((__half2*)dL)[i4 >> 1] = __floats2half2_rn(v.x - f01.x, v.y - f01.y);
        ((__half2*)dL)[(i4 >> 1) + 1] = __floats2half2_rn(v.z - f23.x, v.w - f23.y);
    }
}

// ==================== prep: transpose + split: src[R][Cc] -> dst[Cc][R] ====================
__global__ void __launch_bounds__(256) transpose_split(
    const float* __restrict__ src, __half* __restrict__ dH, __half* __restrict__ dL,
    int R, int Cc)
{
    __shared__ float t[32][33];
    const size_t base = (size_t)blockIdx.z * R * Cc;
    const int r0 = blockIdx.x * 32, c0 = blockIdx.y * 32;
    const int x = threadIdx.x, y = threadIdx.y;
#pragma unroll
    for (int i = 0; i < 32; i += 8)
        t[y + i][x] = src[base + (size_t)(r0 + y + i) * Cc + c0 + x];
    __syncthreads();
#pragma unroll
    for (int i = 0; i < 32; i += 8) {
        const float v = t[x][y + i];
        const __half h = __float2half_rn(v);
        const size_t idx = base + (size_t)(c0 + y + i) * R + r0 + x;
        dH[idx] = h;
        if (dL) dL[idx] = __float2half_rn(v - __half2float(h));
    }
}

// ==================== softmax (fp32 + fp16 hi out) ====================
__global__ void __launch_bounds__(256) k3_softmax(
    float* __restrict__ a, __half* __restrict__ aH)
{
    const size_t row = blockIdx.x;
    float* p = a + row * SS;
    const int tid = threadIdx.x;
    float v[8];
#pragma unroll
    for (int i = 0; i < 8; i++) v[i] = p[tid + (i << 8)];
    float m = v[0];
#pragma unroll
    for (int i = 1; i < 8; i++) m = fmaxf(m, v[i]);
#pragma unroll
    for (int o = 16; o > 0; o >>= 1) m = fmaxf(m, __shfl_xor_sync(0xffffffffu, m, o));
    __shared__ float red[8];
    if ((tid & 31) == 0) red[tid >> 5] = m;
    __syncthreads();
    float M = red[0];
#pragma unroll
    for (int i = 1; i < 8; i++) M = fmaxf(M, red[i]);
    float s = 0.f;
#pragma unroll
    for (int i = 0; i < 8; i++) { v[i] = __expf(v[i] - M); s += v[i]; }
#pragma unroll
    for (int o = 16; o > 0; o >>= 1) s += __shfl_xor_sync(0xffffffffu, s, o);
    __syncthreads();
    if ((tid & 31) == 0) red[tid >> 5] = s;
    __syncthreads();
    float Z = 0.f;
#pragma unroll
    for (int i = 0; i < 8; i++) Z += red[i];
    const float inv = 1.f / Z;
#pragma unroll
    for (int i = 0; i < 8; i++) {
        const float q = v[i] * inv;
        p[tid + (i << 8)] = q;
        aH[row * SS + tid + (i << 8)] = __float2half_rn(q);
    }
}

extern "C" void kernel_launch(void* const* d_in, const int* in_sizes, int n_in,
                              void* d_out, int out_size)
{
    const float* dec  = (const float*)d_in[0];
    const float* emb  = (const float*)d_in[1];
    const float* enc  = (const float*)d_in[2];
    const float* enb  = (const float*)d_in[3];
    const float* Wh2e = (const float*)d_in[4];
    const float* bh2e = (const float*)d_in[5];
    const float* We2h = (const float*)d_in[6];
    const float* be2h = (const float*)d_in[7];
    float* a_out    = (float*)d_out;                 // [B,T,S]
    float* conv_out = a_out + (size_t)BB * TT * SS;  // [B,H,T]

    cudaFuncSetAttribute((const void*)gemmh<3>,
                         cudaFuncAttributeMaxDynamicSharedMemorySize, GEMMH_SMEM);
    cudaFuncSetAttribute((const void*)gemmh<1>,
                         cudaFuncAttributeMaxDynamicSharedMemorySize, GEMMH_SMEM);

#define SYM(p, s) __half* p = nullptr; cudaGetSymbolAddress((void**)&p, s)
    SYM(QH, g_QH);  SYM(QL, g_QL);
    SYM(aH, g_aH);
    SYM(cH, g_cH);
    SYM(VtH, g_VtH);
    SYM(dtH, g_dtH); SYM(dtL, g_dtL);
    SYM(KHp, g_KH); SYM(KLp, g_KL);
    SYM(WqH, g_WqH); SYM(WqL, g_WqL);
    SYM(WoH, g_WoH);
#undef SYM

    // ---- forked-stream pipeline (graph-capturable: event fork/join) ----
    cudaStream_t sB;
    cudaStreamCreateWithFlags(&sB, cudaStreamNonBlocking);
    cudaEvent_t evRoot, evEnc, evJoin, ev2[BB];
    cudaEventCreateWithFlags(&evRoot, cudaEventDisableTiming);
    cudaEventCreateWithFlags(&evEnc,  cudaEventDisableTiming);
    cudaEventCreateWithFlags(&evJoin, cudaEventDisableTiming);
    for (int b = 0; b < BB; b++)
        cudaEventCreateWithFlags(&ev2[b], cudaEventDisableTiming);

    cudaEventRecord(evRoot, 0);
    cudaStreamWaitEvent(sB, evRoot, 0);

    // sB: K/V/Wo prep (overlaps k1 chain on s0)
    split_plain<<<BB * SS * EE / 1024, 256, 0, sB>>>(enc, KHp, KLp);
    cudaEventRecord(evEnc, sB);
    transpose_split<<<dim3(SS / 32, EE / 32, BB), dim3(32, 8), 0, sB>>>(enb, VtH, nullptr, SS, EE);
    split_plain<<<HH * EE / 1024, 256, 0, sB>>>(We2h, WoH, nullptr);

    // s0: Q-side prep + K1 (3-term, batched)
    split_plain<<<EE * HH / 1024, 256>>>(Wh2e, WqH, WqL);
    transpose_split<<<dim3(HH / 32, TT / 32, BB), dim3(32, 8)>>>(dec, dtH, dtL, HH, TT);
    gemmh<3><<<dim3(EE / 128, TT / 128, BB), 256, GEMMH_SMEM>>>(
        dtH, dtL, HH, (size_t)TT * HH,
        WqH, WqL, HH, 0,
        nullptr, QH, QL, EE, (size_t)TT * EE,
        HH, 1, bh2e, emb, EE, (size_t)TT * EE);

    // s0: K2 per batch, signaling sB
    cudaStreamWaitEvent(0, evEnc, 0);
    for (int b = 0; b < BB; b++) {
        gemmh<3><<<dim3(SS / 128, TT / 128, 1), 256, GEMMH_SMEM>>>(
            QH + (size_t)b * TT * EE, QL + (size_t)b * TT * EE, EE, 0,
            KHp + (size_t)b * SS * EE, KLp + (size_t)b * SS * EE, EE, 0,
            a_out + (size_t)b * TT * SS, nullptr, nullptr, SS, 0,
            EE, 0, nullptr, nullptr, 0, 0);
        cudaEventRecord(ev2[b], 0);
    }

    // sB: per-batch softmax -> k4 -> k5 trailing the k2 launches
    for (int b = 0; b < BB; b++) {
        cudaStreamWaitEvent(sB, ev2[b], 0);
        k3_softmax<<<TT, 256, 0, sB>>>(
            a_out + (size_t)b * TT * SS, aH + (size_t)b * TT * SS);
        gemmh<1><<<dim3(EE / 128, TT / 128, 1), 256, GEMMH_SMEM, sB>>>(
            aH + (size_t)b * TT * SS, nullptr, SS, 0,
            VtH + (size_t)b * EE * SS, nullptr, SS, 0,
            nullptr, cH + (size_t)b * TT * EE, nullptr, EE, 0,
            SS, 3, nullptr, nullptr, 0, 0);
        gemmh<1><<<dim3(HH / 128, TT / 128, 1), 256, GEMMH_SMEM, sB>>>(
            cH + (size_t)b * TT * EE, nullptr, EE, 0,
            WoH, nullptr, EE, 0,
            conv_out + (size_t)b * HH * TT, nullptr, nullptr, TT, 0,
            EE, 2, be2h, dec + (size_t)b * HH * TT, TT, 0);
    }
    cudaEventRecord(evJoin, sB);
    cudaStreamWaitEvent(0, evJoin, 0);
    // streams/events intentionally not destroyed (capture-safe; few calls total)
}

// round 16
// speedup vs baseline: 1.6738x; 1.6738x over previous
#include <cuda_runtime.h>
#include <cuda_fp16.h>
#include <cstdint>

#define BB 8
#define HH 512
#define EE 256
#define TT 2048
#define SS 2048
#define SCALE 0.8366600265340756f  // sqrt(0.7)

// ---- fp16 hi/lo scratch (device globals; no allocation in kernel_launch) ----
__device__ __half g_QH[BB * TT * EE],  g_QL[BB * TT * EE];
__device__ __half g_aH[(size_t)BB * TT * SS];
__device__ __half g_cH[BB * TT * EE];
__device__ __half g_VtH[BB * EE * SS];
__device__ __half g_dtH[BB * TT * HH], g_dtL[BB * TT * HH];
__device__ __half g_KH[BB * SS * EE],  g_KL[BB * SS * EE];
__device__ __half g_WqH[EE * HH], g_WqL[EE * HH];
__device__ __half g_WoH[HH * EE];

__device__ __forceinline__ uint32_t smem_u32(const void* p) {
    uint32_t a;
    asm("{ .reg .u64 t; cvta.to.shared.u64 t, %1; cvt.u32.u64 %0, t; }" : "=r"(a) : "l"(p));
    return a;
}
#define CPA16(dst, src) \
    asm volatile("cp.async.ca.shared.global [%0], [%1], 16;" :: "r"(dst), "l"(src))
#define CPA_COMMIT() asm volatile("cp.async.commit_group;" ::: "memory")
#define CPA_WAIT(n)  asm volatile("cp.async.wait_group %0;" :: "n"(n) : "memory")
#define LDM4(r0, r1, r2, r3, addr)                                            \
    asm volatile("ldmatrix.sync.aligned.m8n8.x4.shared.b16 {%0,%1,%2,%3}, [%4];" \
        : "=r"(r0), "=r"(r1), "=r"(r2), "=r"(r3) : "r"(addr))
#define MMA16(c, a, b)                                                        \
    asm volatile("mma.sync.aligned.m16n8k16.row.col.f32.f16.f16.f32 "         \
        "{%0,%1,%2,%3},{%4,%5,%6,%7},{%8,%9},{%0,%1,%2,%3};"                  \
        : "+f"((c)[0]), "+f"((c)[1]), "+f"((c)[2]), "+f"((c)[3])              \
        : "r"((a)[0]), "r"((a)[1]), "r"((a)[2]), "r"((a)[3]),                 \
          "r"((b)[0]), "r"((b)[1]))

// ==================== fp16 split GEMM ====================
// C[m,n] = sum_k A[m,k]*B[n,k]; A/B K-major fp16 hi(+lo).
// TERMS==3: Ah*Bh + Al*Bh + Ah*Bl (all f32 acc).  TERMS==1: Ah*Bh.
// 256 thr = 8 warps (2x4), warp tile 64x32, BK=32, cp.async double-buffered.
// Single __syncthreads per chunk: prefetch for c+1 issued AFTER the sync
// (all warps have finished reading buffer (c+1)&1 at that point).
// SMEM stage (pitch 40 halves = 80B): Ah@0, Al@10240, Bh@20480, Bl@30720.
#define STAGE_B 40960
#define GEMMH_SMEM (2 * STAGE_B)

template <int TERMS>
__device__ __forceinline__ void load_tiles(
    uint32_t smb, int st,
    const __half* Ah, const __half* Al, int lda,
    const __half* Bh, const __half* Bl, int ldb,
    int k0, int tid)
{
    const int row = tid >> 1;
    const int hq  = (tid & 1) * 16;
    const uint32_t d0 = smb + (uint32_t)st * STAGE_B + (uint32_t)row * 80u
                        + (uint32_t)(tid & 1) * 32u;
    const size_t sa = (size_t)row * lda + k0 + hq;
    const size_t sb = (size_t)row * ldb + k0 + hq;
    CPA16(d0 +     0, Ah + sa); CPA16(d0 +    16, Ah + sa + 8);
    if (TERMS == 3) {
        CPA16(d0 + 10240, Al + sa); CPA16(d0 + 10256, Al + sa + 8);
        CPA16(d0 + 30720, Bl + sb); CPA16(d0 + 30736, Bl + sb + 8);
    }
    CPA16(d0 + 20480, Bh + sb); CPA16(d0 + 20496, Bh + sb + 8);
}

template <int TERMS>
__global__ void __launch_bounds__(256, 2) gemmh(
    const __half* __restrict__ AH, const __half* __restrict__ AL, int lda, size_t sA,
    const __half* __restrict__ BH, const __half* __restrict__ BL, int ldb, size_t sB,
    float* __restrict__ C, __half* __restrict__ CH, __half* __restrict__ CL,
    int ldc, size_t sC, int K, int mode,
    const float* __restrict__ bias,
    const float* __restrict__ aux, int ldaux, size_t saux)
{
    extern __shared__ __align__(16) char smraw[];
    const uint32_t smb = smem_u32(smraw);

    const int tid  = threadIdx.x;
    const int lane = tid & 31;
    const int wid  = tid >> 5;
    const int mB   = (wid >> 2) * 64;
    const int nB   = (wid & 3) * 32;
    const int g    = lane >> 2;
    const int tg   = lane & 3;
    const int l15  = lane & 15;
    const int lhi  = lane >> 4;

    const uint32_t aoff = (uint32_t)((mB + l15) * 80 + lhi * 16);
    const uint32_t boff = (uint32_t)((nB + l15) * 80 + lhi * 16);

    const int bz = blockIdx.z;
    const __half* Ah = AH + bz * sA + (size_t)(blockIdx.y * 128) * lda;
    const __half* Al = (TERMS == 3) ? AL + bz * sA + (size_t)(blockIdx.y * 128) * lda : nullptr;
    const __half* Bh = BH + bz * sB + (size_t)(blockIdx.x * 128) * ldb;
    const __half* Bl = (TERMS == 3) ? BL + bz * sB + (size_t)(blockIdx.x * 128) * ldb : nullptr;

    const int NC = K >> 5;
    float acc[4][4][4] = {};

    load_tiles<TERMS>(smb, 0, Ah, Al, lda, Bh, Bl, ldb, 0, tid);
    CPA_COMMIT();

    for (int c = 0; c < NC; c++) {
        CPA_WAIT(0);          // stage c data complete (only group in flight)
        __syncthreads();      // also: all warps done reading buffer (c+1)&1
        if (c + 1 < NC) {
            load_tiles<TERMS>(smb, (c + 1) & 1, Ah, Al, lda, Bh, Bl, ldb, (c + 1) << 5, tid);
            CPA_COMMIT();
        }

        const uint32_t sb = smb + (uint32_t)(c & 1) * STAGE_B;
#pragma unroll
        for (int ks = 0; ks < 2; ks++) {
            const uint32_t ko = (uint32_t)ks * 32;
            uint32_t ah[4][4], al[4][4], bh[4][2], bl[4][2];
#pragma unroll
            for (int mi = 0; mi < 4; mi++) {
                LDM4(ah[mi][0], ah[mi][1], ah[mi][2], ah[mi][3],
                     sb + aoff + (uint32_t)mi * 1280 + ko);
                if (TERMS == 3)
                    LDM4(al[mi][0], al[mi][1], al[mi][2], al[mi][3],
                         sb + 10240 + aoff + (uint32_t)mi * 1280 + ko);
            }
#pragma unroll
            for (int nj = 0; nj < 2; nj++)
                LDM4(bh[2 * nj][0], bh[2 * nj + 1][0], bh[2 * nj][1], bh[2 * nj + 1][1],
                     sb + 20480 + boff + (uint32_t)nj * 1280 + ko);
            if (TERMS == 3) {
#pragma unroll
                for (int nj = 0; nj < 2; nj++)
                    LDM4(bl[2 * nj][0], bl[2 * nj + 1][0], bl[2 * nj][1], bl[2 * nj + 1][1],
                         sb + 30720 + boff + (uint32_t)nj * 1280 + ko);
            }

            // pass 1: hh
#pragma unroll
            for (int mi = 0; mi < 4; mi++)
#pragma unroll
                for (int ni = 0; ni < 4; ni++)
                    MMA16(acc[mi][ni], ah[mi], bh[ni]);
            if (TERMS == 3) {
                // pass 2: lh
#pragma unroll
                for (int mi = 0; mi < 4; mi++)
#pragma unroll
                    for (int ni = 0; ni < 4; ni++)
                        MMA16(acc[mi][ni], al[mi], bh[ni]);
                // pass 3: hl
#pragma unroll
                for (int mi = 0; mi < 4; mi++)
#pragma unroll
                    for (int ni = 0; ni < 4; ni++)
                        MMA16(acc[mi][ni], ah[mi], bl[ni]);
            }
        }
    }

    // ---- epilogue ----
    if (mode == 0) {
        // plain fp32 store (energy)
        float* Cb = C + bz * sC;
#pragma unroll
        for (int mi = 0; mi < 4; mi++) {
            const int r = blockIdx.y * 128 + mB + mi * 16 + g;
#pragma unroll
            for (int ni = 0; ni < 4; ni++) {
                const int cc = blockIdx.x * 128 + nB + ni * 8 + 2 * tg;
                float2 v0 = {acc[mi][ni][0], acc[mi][ni][1]};
                float2 v1 = {acc[mi][ni][2], acc[mi][ni][3]};
                *(float2*)(Cb + (size_t)r * ldc + cc) = v0;
                *(float2*)(Cb + (size_t)(r + 8) * ldc + cc) = v1;
            }
        }
    } else if (mode == 2) {
        // transposed fp32 store + bias + residual + scale (output projection)
        float* Cb = C + bz * sC;
        const float* Db = aux + bz * saux;
#pragma unroll
        for (int mi = 0; mi < 4; mi++) {
            const int r = blockIdx.y * 128 + mB + mi * 16 + g;
#pragma unroll
            for (int ni = 0; ni < 4; ni++) {
                const int cc = blockIdx.x * 128 + nB + ni * 8 + 2 * tg;
                const float b0 = bias[cc], b1 = bias[cc + 1];
                Cb[(size_t)cc * ldc + r] =
                    SCALE * (acc[mi][ni][0] + b0 + Db[(size_t)cc * ldaux + r]);
                Cb[(size_t)(cc + 1) * ldc + r] =
                    SCALE * (acc[mi][ni][1] + b1 + Db[(size_t)(cc + 1) * ldaux + r]);
                Cb[(size_t)cc * ldc + r + 8] =
                    SCALE * (acc[mi][ni][2] + b0 + Db[(size_t)cc * ldaux + r + 8]);
                Cb[(size_t)(cc + 1) * ldc + r + 8] =
                    SCALE * (acc[mi][ni][3] + b1 + Db[(size_t)(cc + 1) * ldaux + r + 8]);
            }
        }
    } else if (mode == 1) {
        // fp16 hi/lo store + bias + emb + scale (Q projection)
        __half* CHb = CH + bz * sC;
        __half* CLb = CL + bz * sC;
#pragma unroll
        for (int mi = 0; mi < 4; mi++) {
            const int r = blockIdx.y * 128 + mB + mi * 16 + g;
#pragma unroll
            for (int ni = 0; ni < 4; ni++) {
                const int cc = blockIdx.x * 128 + nB + ni * 8 + 2 * tg;
                const float2 bi = *(const float2*)(bias + cc);
                const float2 e0 = *(const float2*)(aux + bz * saux + (size_t)r * ldaux + cc);
                const float2 e1 = *(const float2*)(aux + bz * saux + (size_t)(r + 8) * ldaux + cc);
                float q0 = SCALE * (acc[mi][ni][0] + bi.x + e0.x);
                float q1 = SCALE * (acc[mi][ni][1] + bi.y + e0.y);
                float q2 = SCALE * (acc[mi][ni][2] + bi.x + e1.x);
                float q3 = SCALE * (acc[mi][ni][3] + bi.y + e1.y);
                __half2 h0 = __floats2half2_rn(q0, q1);
                float2 f0 = __half22float2(h0);
                __half2 l0 = __floats2half2_rn(q0 - f0.x, q1 - f0.y);
                __half2 h1 = __floats2half2_rn(q2, q3);
                float2 f1 = __half22float2(h1);
                __half2 l1 = __floats2half2_rn(q2 - f1.x, q3 - f1.y);
                *(__half2*)(CHb + (size_t)r * ldc + cc) = h0;
                *(__half2*)(CLb + (size_t)r * ldc + cc) = l0;
                *(__half2*)(CHb + (size_t)(r + 8) * ldc + cc) = h1;
                *(__half2*)(CLb + (size_t)(r + 8) * ldc + cc) = l1;
            }
        }
    } else {
        // mode 3: fp16 hi-only store (context)
        __half* CHb = CH + bz * sC;
#pragma unroll
        for (int mi = 0; mi < 4; mi++) {
            const int r = blockIdx.y * 128 + mB + mi * 16 + g;
#pragma unroll
            for (int ni = 0; ni < 4; ni++) {
                const int cc = blockIdx.x * 128 + nB + ni * 8 + 2 * tg;
                *(__half2*)(CHb + (size_t)r * ldc + cc) =
                    __floats2half2_rn(acc[mi][ni][0], acc[mi][ni][1]);
                *(__half2*)(CHb + (size_t)(r + 8) * ldc + cc) =
                    __floats2half2_rn(acc[mi][ni][2], acc[mi][ni][3]);
            }
        }
    }
}

// ==================== prep: elementwise fp32 -> hi(+lo) fp16 ====================
__global__ void __launch_bounds__(256) split_plain(
    const float* __restrict__ s, __half* __restrict__ dH, __half* __restrict__ dL)
{
    const size_t i4 = ((size_t)blockIdx.x * 256 + threadIdx.x) * 4;
    float4 v = *(const float4*)(s + i4);
    __half2 h01 = __floats2half2_rn(v.x, v.y);
    __half2 h23 = __floats2half2_rn(v.z, v.w);
    ((__half2*)dH)[i4 >> 1] = h01; ((__half2*)dH)[(i4 >> 1) + 1] = h23;
    if (dL) {
        float2 f01 = __half22float2(h01);
        float2 f23 = __half22float2(h23);
        ((__half2*)dL)[i4 >> 1] = __floats2half2_rn(v.x - f01.x, v.y - f01.y);
        ((__half2*)dL)[(i4 >> 1) + 1] = __floats2half2_rn(v.z - f23.x, v.w - f23.y);
    }
}

// ==================== prep: transpose + split: src[R][Cc] -> dst[Cc][R] ====================
__global__ void __launch_bounds__(256) transpose_split(
    const float* __restrict__ src, __half* __restrict__ dH, __half* __restrict__ dL,
    int R, int Cc)
{
    __shared__ float t[32][33];
    const size_t base = (size_t)blockIdx.z * R * Cc;
    const int r0 = blockIdx.x * 32, c0 = blockIdx.y * 32;
    const int x = threadIdx.x, y = threadIdx.y;
#pragma unroll
    for (int i = 0; i < 32; i += 8)
        t[y + i][x] = src[base + (size_t)(r0 + y + i) * Cc + c0 + x];
    __syncthreads();
#pragma unroll
    for (int i = 0; i < 32; i += 8) {
        const float v = t[x][y + i];
        const __half h = __float2half_rn(v);
        const size_t idx = base + (size_t)(c0 + y + i) * R + r0 + x;
        dH[idx] = h;
        if (dL) dL[idx] = __float2half_rn(v - __half2float(h));
    }
}

// ==================== softmax (fp32 + fp16 hi out) — R9 interleaved ====================
__global__ void __launch_bounds__(256) k3_softmax(
    float* __restrict__ a, __half* __restrict__ aH)
{
    const size_t row = blockIdx.x;
    float* p = a + row * SS;
    const int tid = threadIdx.x;
    float v[8];
#pragma unroll
    for (int i = 0; i < 8; i++) v[i] = p[tid + (i << 8)];
    float m = v[0];
#pragma unroll
    for (int i = 1; i < 8; i++) m = fmaxf(m, v[i]);
#pragma unroll
    for (int o = 16; o > 0; o >>= 1) m = fmaxf(m, __shfl_xor_sync(0xffffffffu, m, o));
    __shared__ float red[8];
    if ((tid & 31) == 0) red[tid >> 5] = m;
    __syncthreads();
    float M = red[0];
#pragma unroll
    for (int i = 1; i < 8; i++) M = fmaxf(M, red[i]);
    float s = 0.f;
#pragma unroll
    for (int i = 0; i < 8; i++) { v[i] = __expf(v[i] - M); s += v[i]; }
#pragma unroll
    for (int o = 16; o > 0; o >>= 1) s += __shfl_xor_sync(0xffffffffu, s, o);
    __syncthreads();
    if ((tid & 31) == 0) red[tid >> 5] = s;
    __syncthreads();
    float Z = 0.f;
#pragma unroll
    for (int i = 0; i < 8; i++) Z += red[i];
    const float inv = 1.f / Z;
#pragma unroll
    for (int i = 0; i < 8; i++) {
        const float q = v[i] * inv;
        p[tid + (i << 8)] = q;
        aH[row * SS + tid + (i << 8)] = __float2half_rn(q);
    }
}

extern "C" void kernel_launch(void* const* d_in, const int* in_sizes, int n_in,
                              void* d_out, int out_size)
{
    const float* dec  = (const float*)d_in[0];
    const float* emb  = (const float*)d_in[1];
    const float* enc  = (const float*)d_in[2];
    const float* enb  = (const float*)d_in[3];
    const float* Wh2e = (const float*)d_in[4];
    const float* bh2e = (const float*)d_in[5];
    const float* We2h = (const float*)d_in[6];
    const float* be2h = (const float*)d_in[7];
    float* a_out    = (float*)d_out;                 // [B,T,S]
    float* conv_out = a_out + (size_t)BB * TT * SS;  // [B,H,T]

    cudaFuncSetAttribute((const void*)gemmh<3>,
                         cudaFuncAttributeMaxDynamicSharedMemorySize, GEMMH_SMEM);
    cudaFuncSetAttribute((const void*)gemmh<1>,
                         cudaFuncAttributeMaxDynamicSharedMemorySize, GEMMH_SMEM);

#define SYM(p, s) __half* p = nullptr; cudaGetSymbolAddress((void**)&p, s)
    SYM(QH, g_QH);  SYM(QL, g_QL);
    SYM(aH, g_aH);
    SYM(cH, g_cH);
    SYM(VtH, g_VtH);
    SYM(dtH, g_dtH); SYM(dtL, g_dtL);
    SYM(KHp, g_KH); SYM(KLp, g_KL);
    SYM(WqH, g_WqH); SYM(WqL, g_WqL);
    SYM(WoH, g_WoH);
#undef SYM

    // prep: splits + transposes (lo plane only where needed)
    split_plain<<<BB * SS * EE / 1024, 256>>>(enc, KHp, KLp);
    split_plain<<<EE * HH / 1024, 256>>>(Wh2e, WqH, WqL);
    split_plain<<<HH * EE / 1024, 256>>>(We2h, WoH, nullptr);
    transpose_split<<<dim3(SS / 32, EE / 32, BB), dim3(32, 8)>>>(enb, VtH, nullptr, SS, EE);
    transpose_split<<<dim3(HH / 32, TT / 32, BB), dim3(32, 8)>>>(dec, dtH, dtL, HH, TT);

    // K1 (3-term): Q = SCALE*(dec^T @ Wq^T + bias + emb) -> fp16 hi/lo
    gemmh<3><<<dim3(EE / 128, TT / 128, BB), 256, GEMMH_SMEM>>>(
        dtH, dtL, HH, (size_t)TT * HH,
        WqH, WqL, HH, 0,
        nullptr, QH, QL, EE, (size_t)TT * EE,
        HH, 1, bh2e, emb, EE, (size_t)TT * EE);

    // K2 (3-term): energy = Q @ K^T -> fp32 a_out (raw)
    gemmh<3><<<dim3(SS / 128, TT / 128, BB), 256, GEMMH_SMEM>>>(
        QH, QL, EE, (size_t)TT * EE,
        KHp, KLp, EE, (size_t)SS * EE,
        a_out, nullptr, nullptr, SS, (size_t)TT * SS,
        EE, 0, nullptr, nullptr, 0, 0);

    k3_softmax<<<BB * TT, 256>>>(a_out, aH);

    // K4 (1-term): ctx = a @ Vh -> fp16 hi only
    gemmh<1><<<dim3(EE / 128, TT / 128, BB), 256, GEMMH_SMEM>>>(
        aH, nullptr, SS, (size_t)TT * SS,
        VtH, nullptr, SS, (size_t)EE * SS,
        nullptr, cH, nullptr, EE, (size_t)TT * EE,
        SS, 3, nullptr, nullptr, 0, 0);

    // K5 (1-term): out = SCALE*(ctx @ WoH^T + bias + dec), transposed store
    gemmh<1><<<dim3(HH / 128, TT / 128, BB), 256, GEMMH_SMEM>>>(
        cH, nullptr, EE, (size_t)TT * EE,
        WoH, nullptr, EE, 0,
        conv_out, nullptr, nullptr, TT, (size_t)HH * TT,
        EE, 2, be2h, dec, TT, (size_t)HH * TT);
}

// round 17
// speedup vs baseline: 1.6780x; 1.0026x over previous
#include <cuda_runtime.h>
#include <cuda_fp16.h>
#include <cstdint>

#define BB 8
#define HH 512
#define EE 256
#define TT 2048
#define SS 2048
#define SCALE 0.8366600265340756f  // sqrt(0.7)

// ---- fp16 hi/lo scratch (device globals; no allocation in kernel_launch) ----
__device__ __half g_QH[BB * TT * EE],  g_QL[BB * TT * EE];
__device__ __half g_aH[(size_t)BB * TT * SS];
__device__ __half g_cH[BB * TT * EE];
__device__ __half g_VtH[BB * EE * SS];
__device__ __half g_dtH[BB * TT * HH], g_dtL[BB * TT * HH];
__device__ __half g_KH[BB * SS * EE],  g_KL[BB * SS * EE];
__device__ __half g_WqH[EE * HH], g_WqL[EE * HH];
__device__ __half g_WoH[HH * EE];

__device__ __forceinline__ uint32_t smem_u32(const void* p) {
    uint32_t a;
    asm("{ .reg .u64 t; cvta.to.shared.u64 t, %1; cvt.u32.u64 %0, t; }" : "=r"(a) : "l"(p));
    return a;
}
#define CPA16(dst, src) \
    asm volatile("cp.async.ca.shared.global [%0], [%1], 16;" :: "r"(dst), "l"(src))
#define CPA_COMMIT() asm volatile("cp.async.commit_group;" ::: "memory")
#define CPA_WAIT(n)  asm volatile("cp.async.wait_group %0;" :: "n"(n) : "memory")
#define LDM4(r0, r1, r2, r3, addr)                                            \
    asm volatile("ldmatrix.sync.aligned.m8n8.x4.shared.b16 {%0,%1,%2,%3}, [%4];" \
        : "=r"(r0), "=r"(r1), "=r"(r2), "=r"(r3) : "r"(addr))
#define MMA16(c, a, b)                                                        \
    asm volatile("mma.sync.aligned.m16n8k16.row.col.f32.f16.f16.f32 "         \
        "{%0,%1,%2,%3},{%4,%5,%6,%7},{%8,%9},{%0,%1,%2,%3};"                  \
        : "+f"((c)[0]), "+f"((c)[1]), "+f"((c)[2]), "+f"((c)[3])              \
        : "r"((a)[0]), "r"((a)[1]), "r"((a)[2]), "r"((a)[3]),                 \
          "r"((b)[0]), "r"((b)[1]))

// ==================== fp16 split GEMM ====================
// C[m,n] = sum_k A[m,k]*B[n,k]; A/B K-major fp16 hi(+lo).
// TERMS==3: Ah*Bh + Al*Bh + Ah*Bl (all f32 acc).  TERMS==1: Ah*Bh.
// 256 thr = 8 warps (2x4), warp tile 64x32, BK=32, cp.async double-buffered.
// SMEM stage (pitch 40 halves = 80B): Ah@0, Al@10240, Bh@20480, Bl@30720.
#define STAGE_B 40960
#define GEMMH_SMEM (2 * STAGE_B)

template <int TERMS>
__device__ __forceinline__ void load_tiles(
    uint32_t smb, int st,
    const __half* Ah, const __half* Al, int lda,
    const __half* Bh, const __half* Bl, int ldb,
    int k0, int tid)
{
    const int row = tid >> 1;
    const int hq  = (tid & 1) * 16;
    const uint32_t d0 = smb + (uint32_t)st * STAGE_B + (uint32_t)row * 80u
                        + (uint32_t)(tid & 1) * 32u;
    const size_t sa = (size_t)row * lda + k0 + hq;
    const size_t sb = (size_t)row * ldb + k0 + hq;
    CPA16(d0 +     0, Ah + sa); CPA16(d0 +    16, Ah + sa + 8);
    if (TERMS == 3) {
        CPA16(d0 + 10240, Al + sa); CPA16(d0 + 10256, Al + sa + 8);
        CPA16(d0 + 30720, Bl + sb); CPA16(d0 + 30736, Bl + sb + 8);
    }
    CPA16(d0 + 20480, Bh + sb); CPA16(d0 + 20496, Bh + sb + 8);
}

template <int TERMS>
__global__ void __launch_bounds__(256, 2) gemmh(
    const __half* __restrict__ AH, const __half* __restrict__ AL, int lda, size_t sA,
    const __half* __restrict__ BH, const __half* __restrict__ BL, int ldb, size_t sB,
    float* __restrict__ C, __half* __restrict__ CH, __half* __restrict__ CL,
    int ldc, size_t sC, int K, int mode,
    const float* __restrict__ bias,
    const float* __restrict__ aux, int ldaux, size_t saux)
{
    extern __shared__ __align__(16) char smraw[];
    const uint32_t smb = smem_u32(smraw);

    const int tid  = threadIdx.x;
    const int lane = tid & 31;
    const int wid  = tid >> 5;
    const int mB   = (wid >> 2) * 64;
    const int nB   = (wid & 3) * 32;
    const int g    = lane >> 2;
    const int tg   = lane & 3;
    const int l15  = lane & 15;
    const int lhi  = lane >> 4;

    const uint32_t aoff = (uint32_t)((mB + l15) * 80 + lhi * 16);
    const uint32_t boff = (uint32_t)((nB + l15) * 80 + lhi * 16);

    const int bz = blockIdx.z;
    const __half* Ah = AH + bz * sA + (size_t)(blockIdx.y * 128) * lda;
    const __half* Al = (TERMS == 3) ? AL + bz * sA + (size_t)(blockIdx.y * 128) * lda : nullptr;
    const __half* Bh = BH + bz * sB + (size_t)(blockIdx.x * 128) * ldb;
    const __half* Bl = (TERMS == 3) ? BL + bz * sB + (size_t)(blockIdx.x * 128) * ldb : nullptr;

    const int NC = K >> 5;
    float acc[4][4][4] = {};

    load_tiles<TERMS>(smb, 0, Ah, Al, lda, Bh, Bl, ldb, 0, tid);
    CPA_COMMIT();

    for (int c = 0; c < NC; c++) {
        if (c + 1 < NC) {
            load_tiles<TERMS>(smb, (c + 1) & 1, Ah, Al, lda, Bh, Bl, ldb, (c + 1) << 5, tid);
            CPA_COMMIT();
            CPA_WAIT(1);
        } else {
            CPA_WAIT(0);
        }
        __syncthreads();

        const uint32_t sb = smb + (uint32_t)(c & 1) * STAGE_B;
#pragma unroll
        for (int ks = 0; ks < 2; ks++) {
            const uint32_t ko = (uint32_t)ks * 32;
            uint32_t ah[4][4], al[4][4], bh[4][2], bl[4][2];
#pragma unroll
            for (int mi = 0; mi < 4; mi++) {
                LDM4(ah[mi][0], ah[mi][1], ah[mi][2], ah[mi][3],
                     sb + aoff + (uint32_t)mi * 1280 + ko);
                if (TERMS == 3)
                    LDM4(al[mi][0], al[mi][1], al[mi][2], al[mi][3],
                         sb + 10240 + aoff + (uint32_t)mi * 1280 + ko);
            }
#pragma unroll
            for (int nj = 0; nj < 2; nj++)
                LDM4(bh[2 * nj][0], bh[2 * nj + 1][0], bh[2 * nj][1], bh[2 * nj + 1][1],
                     sb + 20480 + boff + (uint32_t)nj * 1280 + ko);
            if (TERMS == 3) {
#pragma unroll
                for (int nj = 0; nj < 2; nj++)
                    LDM4(bl[2 * nj][0], bl[2 * nj + 1][0], bl[2 * nj][1], bl[2 * nj + 1][1],
                         sb + 30720 + boff + (uint32_t)nj * 1280 + ko);
            }

            // pass 1: hh
#pragma unroll
            for (int mi = 0; mi < 4; mi++)
#pragma unroll
                for (int ni = 0; ni < 4; ni++)
                    MMA16(acc[mi][ni], ah[mi], bh[ni]);
            if (TERMS == 3) {
                // pass 2: lh
#pragma unroll
                for (int mi = 0; mi < 4; mi++)
#pragma unroll
                    for (int ni = 0; ni < 4; ni++)
                        MMA16(acc[mi][ni], al[mi], bh[ni]);
                // pass 3: hl
#pragma unroll
                for (int mi = 0; mi < 4; mi++)
#pragma unroll
                    for (int ni = 0; ni < 4; ni++)
                        MMA16(acc[mi][ni], ah[mi], bl[ni]);
            }
        }
        __syncthreads();
    }

    // ---- epilogue ----
    if (mode == 0) {
        // plain fp32 store (energy)
        float* Cb = C + bz * sC;
#pragma unroll
        for (int mi = 0; mi < 4; mi++) {
            const int r = blockIdx.y * 128 + mB + mi * 16 + g;
#pragma unroll
            for (int ni = 0; ni < 4; ni++) {
                const int cc = blockIdx.x * 128 + nB + ni * 8 + 2 * tg;
                float2 v0 = {acc[mi][ni][0], acc[mi][ni][1]};
                float2 v1 = {acc[mi][ni][2], acc[mi][ni][3]};
                *(float2*)(Cb + (size_t)r * ldc + cc) = v0;
                *(float2*)(Cb + (size_t)(r + 8) * ldc + cc) = v1;
            }
        }
    } else if (mode == 2) {
        // transposed fp32 store + bias + residual + scale (output projection)
        float* Cb = C + bz * sC;
        const float* Db = aux + bz * saux;
#pragma unroll
        for (int mi = 0; mi < 4; mi++) {
            const int r = blockIdx.y * 128 + mB + mi * 16 + g;
#pragma unroll
            for (int ni = 0; ni < 4; ni++) {
                const int cc = blockIdx.x * 128 + nB + ni * 8 + 2 * tg;
                const float b0 = bias[cc], b1 = bias[cc + 1];
                Cb[(size_t)cc * ldc + r] =
                    SCALE * (acc[mi][ni][0] + b0 + Db[(size_t)cc * ldaux + r]);
                Cb[(size_t)(cc + 1) * ldc + r] =
                    SCALE * (acc[mi][ni][1] + b1 + Db[(size_t)(cc + 1) * ldaux + r]);
                Cb[(size_t)cc * ldc + r + 8] =
                    SCALE * (acc[mi][ni][2] + b0 + Db[(size_t)cc * ldaux + r + 8]);
                Cb[(size_t)(cc + 1) * ldc + r + 8] =
                    SCALE * (acc[mi][ni][3] + b1 + Db[(size_t)(cc + 1) * ldaux + r + 8]);
            }
        }
    } else if (mode == 1) {
        // fp16 hi/lo store + bias + emb + scale (Q projection)
        __half* CHb = CH + bz * sC;
        __half* CLb = CL + bz * sC;
#pragma unroll
        for (int mi = 0; mi < 4; mi++) {
            const int r = blockIdx.y * 128 + mB + mi * 16 + g;
#pragma unroll
            for (int ni = 0; ni < 4; ni++) {
                const int cc = blockIdx.x * 128 + nB + ni * 8 + 2 * tg;
                const float2 bi = *(const float2*)(bias + cc);
                const float2 e0 = *(const float2*)(aux + bz * saux + (size_t)r * ldaux + cc);
                const float2 e1 = *(const float2*)(aux + bz * saux + (size_t)(r + 8) * ldaux + cc);
                float q0 = SCALE * (acc[mi][ni][0] + bi.x + e0.x);
                float q1 = SCALE * (acc[mi][ni][1] + bi.y + e0.y);
                float q2 = SCALE * (acc[mi][ni][2] + bi.x + e1.x);
                float q3 = SCALE * (acc[mi][ni][3] + bi.y + e1.y);
                __half2 h0 = __floats2half2_rn(q0, q1);
                float2 f0 = __half22float2(h0);
                __half2 l0 = __floats2half2_rn(q0 - f0.x, q1 - f0.y);
                __half2 h1 = __floats2half2_rn(q2, q3);
                float2 f1 = __half22float2(h1);
                __half2 l1 = __floats2half2_rn(q2 - f1.x, q3 - f1.y);
                *(__half2*)(CHb + (size_t)r * ldc + cc) = h0;
                *(__half2*)(CLb + (size_t)r * ldc + cc) = l0;
                *(__half2*)(CHb + (size_t)(r + 8) * ldc + cc) = h1;
                *(__half2*)(CLb + (size_t)(r + 8) * ldc + cc) = l1;
            }
        }
    } else {
        // mode 3: fp16 hi-only store (context)
        __half* CHb = CH + bz * sC;
#pragma unroll
        for (int mi = 0; mi < 4; mi++) {
            const int r = blockIdx.y * 128 + mB + mi * 16 + g;
#pragma unroll
            for (int ni = 0; ni < 4; ni++) {
                const int cc = blockIdx.x * 128 + nB + ni * 8 + 2 * tg;
                *(__half2*)(CHb + (size_t)r * ldc + cc) =
                    __floats2half2_rn(acc[mi][ni][0], acc[mi][ni][1]);
                *(__half2*)(CHb + (size_t)(r + 8) * ldc + cc) =
                    __floats2half2_rn(acc[mi][ni][2], acc[mi][ni][3]);
            }
        }
    }
}

// ==================== prep: elementwise fp32 -> hi(+lo) fp16 ====================
__global__ void __launch_bounds__(256) split_plain(
    const float* __restrict__ s, __half* __restrict__ dH, __half* __restrict__ dL)
{
    const size_t i4 = ((size_t)blockIdx.x * 256 + threadIdx.x) * 4;
    float4 v = *(const float4*)(s + i4);
    __half2 h01 = __floats2half2_rn(v.x, v.y);
    __half2 h23 = __floats2half2_rn(v.z, v.w);
    ((__half2*)dH)[i4 >> 1] = h01; ((__half2*)dH)[(i4 >> 1) + 1] = h23;
    if (dL) {
        float2 f01 = __half22float2(h01);
        float2 f23 = __half22float2(h23);
        ((__half2*)dL)[i4 >> 1] = __floats2half2_rn(v.x - f01.x, v.y - f01.y);
        ((__half2*)dL)[(i4 >> 1) + 1] = __floats2half2_rn(v.z - f23.x, v.w - f23.y);
    }
}

// ==================== prep: transpose + split: src[R][Cc] -> dst[Cc][R] ====================
__global__ void __launch_bounds__(256) transpose_split(
    const float* __restrict__ src, __half* __restrict__ dH, __half* __restrict__ dL,
    int R, int Cc)
{
    __shared__ float t[32][33];
    const size_t base = (size_t)blockIdx.z * R * Cc;
    const int r0 = blockIdx.x * 32, c0 = blockIdx.y * 32;
    const int x = threadIdx.x, y = threadIdx.y;
#pragma unroll
    for (int i = 0; i < 32; i += 8)
        t[y + i][x] = src[base + (size_t)(r0 + y + i) * Cc + c0 + x];
    __syncthreads();
#pragma unroll
    for (int i = 0; i < 32; i += 8) {
        const float v = t[x][y + i];
        const __half h = __float2half_rn(v);
        const size_t idx = base + (size_t)(c0 + y + i) * R + r0 + x;
        dH[idx] = h;
        if (dL) dL[idx] = __float2half_rn(v - __half2float(h));
    }
}

// ==================== softmax (fp32 + fp16 hi out) ====================
__global__ void __launch_bounds__(256) k3_softmax(
    float* __restrict__ a, __half* __restrict__ aH)
{
    const size_t row = blockIdx.x;
    float* p = a + row * SS;
    const int tid = threadIdx.x;
    float v[8];
#pragma unroll
    for (int i = 0; i < 8; i++) v[i] = p[tid + (i << 8)];
    float m = v[0];
#pragma unroll
    for (int i = 1; i < 8; i++) m = fmaxf(m, v[i]);
#pragma unroll
    for (int o = 16; o > 0; o >>= 1) m = fmaxf(m, __shfl_xor_sync(0xffffffffu, m, o));
    __shared__ float red[8];
    if ((tid & 31) == 0) red[tid >> 5] = m;
    __syncthreads();
    float M = red[0];
#pragma unroll
    for (int i = 1; i < 8; i++) M = fmaxf(M, red[i]);
    float s = 0.f;
#pragma unroll
    for (int i = 0; i < 8; i++) { v[i] = __expf(v[i] - M); s += v[i]; }
#pragma unroll
    for (int o = 16; o > 0; o >>= 1) s += __shfl_xor_sync(0xffffffffu, s, o);
    __syncthreads();
    if ((tid & 31) == 0) red[tid >> 5] = s;
    __syncthreads();
    float Z = 0.f;
#pragma unroll
    for (int i = 0; i < 8; i++) Z += red[i];
    const float inv = 1.f / Z;
#pragma unroll
    for (int i = 0; i < 8; i++) {
        const float q = v[i] * inv;
        p[tid + (i << 8)] = q;
        aH[row * SS + tid + (i << 8)] = __float2half_rn(q);
    }
}

extern "C" void kernel_launch(void* const* d_in, const int* in_sizes, int n_in,
                              void* d_out, int out_size)
{
    const float* dec  = (const float*)d_in[0];
    const float* emb  = (const float*)d_in[1];
    const float* enc  = (const float*)d_in[2];
    const float* enb  = (const float*)d_in[3];
    const float* Wh2e = (const float*)d_in[4];
    const float* bh2e = (const float*)d_in[5];
    const float* We2h = (const float*)d_in[6];
    const float* be2h = (const float*)d_in[7];
    float* a_out    = (float*)d_out;                 // [B,T,S]
    float* conv_out = a_out + (size_t)BB * TT * SS;  // [B,H,T]

    cudaFuncSetAttribute((const void*)gemmh<3>,
                         cudaFuncAttributeMaxDynamicSharedMemorySize, GEMMH_SMEM);
    cudaFuncSetAttribute((const void*)gemmh<1>,
                         cudaFuncAttributeMaxDynamicSharedMemorySize, GEMMH_SMEM);

#define SYM(p, s) __half* p = nullptr; cudaGetSymbolAddress((void**)&p, s)
    SYM(QH, g_QH);  SYM(QL, g_QL);
    SYM(aH, g_aH);
    SYM(cH, g_cH);
    SYM(VtH, g_VtH);
    SYM(dtH, g_dtH); SYM(dtL, g_dtL);
    SYM(KHp, g_KH); SYM(KLp, g_KL);
    SYM(WqH, g_WqH); SYM(WqL, g_WqL);
    SYM(WoH, g_WoH);
#undef SYM

    // prep: splits + transposes (lo plane only where needed)
    split_plain<<<BB * SS * EE / 1024, 256>>>(enc, KHp, KLp);
    split_plain<<<EE * HH / 1024, 256>>>(Wh2e, WqH, WqL);
    split_plain<<<HH * EE / 1024, 256>>>(We2h, WoH, nullptr);
    transpose_split<<<dim3(SS / 32, EE / 32, BB), dim3(32, 8)>>>(enb, VtH, nullptr, SS, EE);
    transpose_split<<<dim3(HH / 32, TT / 32, BB), dim3(32, 8)>>>(dec, dtH, dtL, HH, TT);

    // K1 (3-term): Q = SCALE*(dec^T @ Wq^T + bias + emb) -> fp16 hi/lo
    gemmh<3><<<dim3(EE / 128, TT / 128, BB), 256, GEMMH_SMEM>>>(
        dtH, dtL, HH, (size_t)TT * HH,
        WqH, WqL, HH, 0,
        nullptr, QH, QL, EE, (size_t)TT * EE,
        HH, 1, bh2e, emb, EE, (size_t)TT * EE);

    // K2 (3-term): energy = Q @ K^T -> fp32 a_out (raw)
    gemmh<3><<<dim3(SS / 128, TT / 128, BB), 256, GEMMH_SMEM>>>(
        QH, QL, EE, (size_t)TT * EE,
        KHp, KLp, EE, (size_t)SS * EE,
        a_out, nullptr, nullptr, SS, (size_t)TT * SS,
        EE, 0, nullptr, nullptr, 0, 0);

    k3_softmax<<<BB * TT, 256>>>(a_out, aH);

    // K4 (1-term): ctx = a @ Vh -> fp16 hi only
    gemmh<1><<<dim3(EE / 128, TT / 128, BB), 256, GEMMH_SMEM>>>(
        aH, nullptr, SS, (size_t)TT * SS,
        VtH, nullptr, SS, (size_t)EE * SS,
        nullptr, cH, nullptr, EE, (size_t)TT * EE,
        SS, 3, nullptr, nullptr, 0, 0);

    // K5 (1-term): out = SCALE*(ctx @ WoH^T + bias + dec), transposed store
    gemmh<1><<<dim3(HH / 128, TT / 128, BB), 256, GEMMH_SMEM>>>(
        cH, nullptr, EE, (size_t)TT * EE,
        WoH, nullptr, EE, 0,
        conv_out, nullptr, nullptr, TT, (size_t)HH * TT,
        EE, 2, be2h, dec, TT, (size_t)HH * TT);
}